// round 15
// baseline (speedup 1.0000x reference)
#include <cuda_runtime.h>
#include <math.h>

#define N_NODES 50000
#define N_EDGES 800000
#define D 128
#define SCAN_B 1024
#define N_SBLK ((N_NODES + SCAN_B - 1) / SCAN_B)   // 49

// ---------------- scratch (device globals; self-restoring across replays) --
__device__ float g_xT [(size_t)N_NODES * D];   // X transposed: [N,128]
__device__ float g_xw [(size_t)N_NODES * D];   // GEMM out (L1 raw, L2 pre-scaled)
__device__ float g_f1 [(size_t)N_NODES * D];   // layer-1 output
__device__ float g_y  [(size_t)N_NODES * D];   // layer-2 output (+residual)
__device__ float g_deg[N_NODES];               // dinv = rsqrt(1 + in_deg)
__device__ int   g_hist[N_NODES];              // in-degree (zeroed by k_final)
__device__ int   g_rowstart[N_NODES];          // CSR row starts (by dst)
__device__ int   g_cursor[N_NODES];            // fill cursors
__device__ int   g_csrc[N_EDGES];              // CSR src indices
__device__ int   g_bsum[64];                   // scan block sums
__device__ float g_cs [D];                     // col sum of y  (zeroed by gemm L1)
__device__ float g_cs2[D];                     // col sum of y^2

// GELU exact via erff (short polynomial; ~1e-7 abs diff vs normcdff)
__device__ __forceinline__ float gelu_exact(float v) {
    return 0.5f * v * (1.0f + erff(v * 0.70710678118654752f));
}

__device__ __forceinline__ void fma2(unsigned long long& acc,
                                     unsigned long long a,
                                     unsigned long long b) {
    asm("fma.rn.f32x2 %0, %1, %2, %0;" : "+l"(acc) : "l"(a), "l"(b));
}

// ---------------- in-degree histogram (edge_index is INT32) ----------------
__global__ void k_deg(const int* __restrict__ ei) {
    int e = blockIdx.x * blockDim.x + threadIdx.x;
    if (e < N_EDGES) atomicAdd(&g_hist[ei[N_EDGES + e]], 1);
}

// ---------------- scan pass 1 (+ fused dinv = rsqrt(deg+1)) ----------------
__global__ void k_scan1() {
    __shared__ int sh[SCAN_B];
    int t = threadIdx.x;
    int i = blockIdx.x * SCAN_B + t;
    int v = (i < N_NODES) ? g_hist[i] : 0;
    if (i < N_NODES) g_deg[i] = rsqrtf((float)v + 1.0f);
    sh[t] = v;
    __syncthreads();
    for (int off = 1; off < SCAN_B; off <<= 1) {
        int x = (t >= off) ? sh[t - off] : 0;
        __syncthreads();
        sh[t] += x;
        __syncthreads();
    }
    if (i < N_NODES) g_rowstart[i] = sh[t] - v;
    if (t == SCAN_B - 1) g_bsum[blockIdx.x] = sh[t];
}

// ---------------- scan pass 2+3 fused: block offsets + apply ----------------
__global__ void k_scan3() {
    __shared__ int sb[64];
    int t = threadIdx.x;
    if (t < 64) sb[t] = (t < N_SBLK) ? g_bsum[t] : 0;
    __syncthreads();
#pragma unroll
    for (int off = 1; off < 64; off <<= 1) {
        int x = (t < 64 && t >= off) ? sb[t - off] : 0;
        __syncthreads();
        if (t < 64) sb[t] += x;
        __syncthreads();
    }
    int i = blockIdx.x * blockDim.x + t;
    if (i < N_NODES) {
        int blk = i / SCAN_B;
        int add = blk ? sb[blk - 1] : 0;
        int rs = g_rowstart[i] + add;
        g_rowstart[i] = rs;
        g_cursor[i]   = rs;
    }
}

// ---------------- CSR fill ---------------------------------------------------
__global__ void k_fill(const int* __restrict__ ei) {
    int e = blockIdx.x * blockDim.x + threadIdx.x;
    if (e < N_EDGES) {
        int s = ei[e];
        int d = ei[N_EDGES + e];
        int pos = atomicAdd(&g_cursor[d], 1);
        g_csrc[pos] = s;
    }
}

// ---------------- transpose X [128,N] -> xT [N,128] ------------------------
__global__ void k_transpose(const float* __restrict__ X) {
    __shared__ float s[32][33];
    int n0 = blockIdx.x * 32;
    int f0 = blockIdx.y * 32;
    int tx = threadIdx.x, ty = threadIdx.y;          // (32, 8)
    int n = n0 + tx;
#pragma unroll
    for (int i = 0; i < 4; i++) {
        int f = f0 + ty + i * 8;
        if (n < N_NODES) s[ty + i * 8][tx] = X[(size_t)f * N_NODES + n];
    }
    __syncthreads();
#pragma unroll
    for (int i = 0; i < 4; i++) {
        int n2 = n0 + ty + i * 8;
        int f2 = f0 + tx;
        if (n2 < N_NODES) g_xT[(size_t)n2 * D + f2] = s[tx][ty + i * 8];
    }
}

// ---------------- GEMM (f32x2), PDL consumer -------------------------------
// Layer 1 (src_sel=0): g_xw = A @ W          (raw; dinv applied in agg stage 0)
// Layer 2 (src_sel=1): g_xw = (A @ W)*dinv   (pre-scaled fast path)
__global__ void __launch_bounds__(256) k_gemm(int src_sel,
                                              const float* __restrict__ W) {
    const float* __restrict__ A = src_sel ? g_f1 : g_xT;
    int t  = threadIdx.x;
    int tx = t & 15;                   // column group (8 cols)
    int ty = t >> 4;                   // node group (8 nodes)
    int nbase = blockIdx.x * 128;

    // wait for producer (transpose for L1, agg0 for L2) before touching A
    cudaGridDependencySynchronize();

    if (src_sel == 0 && blockIdx.x == 0 && t < D) {
        g_cs[t] = 0.0f;
        g_cs2[t] = 0.0f;
    }
    __shared__ float2 As2[128][16];    // 16 KB: (a,a) pairs, 16-col k-chunk
    __shared__ float  Ws[16][132];     // 8.25 KB padded

    unsigned long long acc[8][4];
#pragma unroll
    for (int i = 0; i < 8; i++)
#pragma unroll
        for (int p = 0; p < 4; p++) acc[i][p] = 0ull;

    for (int fc = 0; fc < D; fc += 16) {
#pragma unroll
        for (int k = 0; k < 8; k++) {           // 128x16 A chunk (dup pairs)
            int idx = t + k * 256;
            int r = idx >> 4, c = idx & 15;
            int n = nbase + r;
            float v = (n < N_NODES) ? A[(size_t)n * D + fc + c] : 0.0f;
            As2[r][c] = make_float2(v, v);
        }
#pragma unroll
        for (int k = 0; k < 8; k++) {           // 16x128 W chunk
            int idx = t + k * 256;
            int r = idx >> 7, c = idx & 127;
            Ws[r][c] = W[(fc + r) * D + c];
        }
        __syncthreads();
#pragma unroll
        for (int ff = 0; ff < 16; ff++) {
            const unsigned long long* wrow =
                (const unsigned long long*)&Ws[ff][tx * 8];
            unsigned long long w0 = wrow[0];
            unsigned long long w1 = wrow[1];
            unsigned long long w2 = wrow[2];
            unsigned long long w3 = wrow[3];
#pragma unroll
            for (int i = 0; i < 8; i++) {
                unsigned long long a2 =
                    *(const unsigned long long*)&As2[ty * 8 + i][ff];
                fma2(acc[i][0], a2, w0);
                fma2(acc[i][1], a2, w1);
                fma2(acc[i][2], a2, w2);
                fma2(acc[i][3], a2, w3);
            }
        }
        __syncthreads();
    }

#pragma unroll
    for (int i = 0; i < 8; i++) {
        int node = nbase + ty * 8 + i;
        if (node >= N_NODES) continue;
        float di = src_sel ? g_deg[node] : 1.0f;
        size_t off = (size_t)node * D + tx * 8;
        float2 p0 = *(float2*)&acc[i][0];
        float2 p1 = *(float2*)&acc[i][1];
        float2 p2 = *(float2*)&acc[i][2];
        float2 p3 = *(float2*)&acc[i][3];
        ((float4*)(g_xw + off))[0] =
            make_float4(p0.x * di, p0.y * di, p1.x * di, p1.y * di);
        ((float4*)(g_xw + off))[1] =
            make_float4(p2.x * di, p2.y * di, p3.x * di, p3.y * di);
    }
}

// ---------------- fused CSR gather + MessageNorm + GELU (+stats) -----------
// stage 0: xw raw   -> msg = dinv[d]*(dinv[d]*xw[d] + sum dinv[s]*xw[s]) + b
// stage 1: xw scaled-> msg = dinv[d]*(xw[d] + sum xw[s]) + b   (+res, +stats)
// PDL consumer: CSR metadata / bias (and xT+xs for stage 0) loaded pre-sync.
__global__ void __launch_bounds__(512) k_agg(int stage,
                                             const float* __restrict__ bias,
                                             const float* __restrict__ scale) {
    __shared__ float s_cs[D], s_cs2[D];
    if (stage) {
        if (threadIdx.x < D) { s_cs[threadIdx.x] = 0.0f; s_cs2[threadIdx.x] = 0.0f; }
        __syncthreads();
    }

    int gw = (blockIdx.x * blockDim.x + threadIdx.x) >> 5;
    int lane = threadIdx.x & 31;
    bool active = gw < N_NODES;
    float4 r = make_float4(0.f, 0.f, 0.f, 0.f);

    // ---- pre-sync prologue: everything independent of the producer GEMM ----
    float nd = 0.0f;
    int rs = 0, end = 0;
    float4 bb = make_float4(0.f, 0.f, 0.f, 0.f);
    float4 xv = make_float4(0.f, 0.f, 0.f, 0.f);
    float xs = 0.0f;
    if (active) {
        nd  = g_deg[gw];
        rs  = g_rowstart[gw];
        end = rs + g_hist[gw];
        bb  = ((const float4*)bias)[lane];
        if (!stage) {   // xT is safe pre-sync for stage 0 (transpose << gemm1)
            xv = ((const float4*)(g_xT + (size_t)gw * D))[lane];
            xs = xv.x*xv.x + xv.y*xv.y + xv.z*xv.z + xv.w*xv.w;
        }
    }
    if (!stage) {
#pragma unroll
        for (int o = 16; o; o >>= 1) xs += __shfl_xor_sync(0xFFFFFFFFu, xs, o);
    }
    float sc = scale[0];

    // ---- wait for producer GEMM's xw (and agg0's f1 for stage 1) ----
    cudaGridDependencySynchronize();

    if (active) {
        const float4* xw4 = (const float4*)g_xw;
        float4 acc = xw4[(size_t)gw * 32 + lane];       // self-loop term
        if (!stage) { acc.x *= nd; acc.y *= nd; acc.z *= nd; acc.w *= nd; }
        int e = rs;
        if (stage) {
            for (; e < end && (e & 3); e++) {
                float4 v = xw4[(size_t)g_csrc[e] * 32 + lane];
                acc.x += v.x; acc.y += v.y; acc.z += v.z; acc.w += v.w;
            }
            for (; e + 8 <= end; e += 8) {
                int4 ia = *(const int4*)&g_csrc[e];
                int4 ib = *(const int4*)&g_csrc[e + 4];
                float4 v0 = xw4[(size_t)ia.x * 32 + lane];
                float4 v1 = xw4[(size_t)ia.y * 32 + lane];
                float4 v2 = xw4[(size_t)ia.z * 32 + lane];
                float4 v3 = xw4[(size_t)ia.w * 32 + lane];
                float4 v4 = xw4[(size_t)ib.x * 32 + lane];
                float4 v5 = xw4[(size_t)ib.y * 32 + lane];
                float4 v6 = xw4[(size_t)ib.z * 32 + lane];
                float4 v7 = xw4[(size_t)ib.w * 32 + lane];
                acc.x += ((v0.x + v1.x) + (v2.x + v3.x)) + ((v4.x + v5.x) + (v6.x + v7.x));
                acc.y += ((v0.y + v1.y) + (v2.y + v3.y)) + ((v4.y + v5.y) + (v6.y + v7.y));
                acc.z += ((v0.z + v1.z) + (v2.z + v3.z)) + ((v4.z + v5.z) + (v6.z + v7.z));
                acc.w += ((v0.w + v1.w) + (v2.w + v3.w)) + ((v4.w + v5.w) + (v6.w + v7.w));
            }
            for (; e < end; e++) {
                float4 v = xw4[(size_t)g_csrc[e] * 32 + lane];
                acc.x += v.x; acc.y += v.y; acc.z += v.z; acc.w += v.w;
            }
        } else {
            for (; e < end && (e & 3); e++) {
                int s0 = g_csrc[e];
                float n0 = g_deg[s0];
                float4 v = xw4[(size_t)s0 * 32 + lane];
                acc.x += v.x*n0; acc.y += v.y*n0; acc.z += v.z*n0; acc.w += v.w*n0;
            }
            for (; e + 4 <= end; e += 4) {
                int4 ia = *(const int4*)&g_csrc[e];
                float n0 = g_deg[ia.x], n1 = g_deg[ia.y];
                float n2 = g_deg[ia.z], n3 = g_deg[ia.w];
                float4 v0 = xw4[(size_t)ia.x * 32 + lane];
                float4 v1 = xw4[(size_t)ia.y * 32 + lane];
                float4 v2 = xw4[(size_t)ia.z * 32 + lane];
                float4 v3 = xw4[(size_t)ia.w * 32 + lane];
                acc.x += (v0.x*n0 + v1.x*n1) + (v2.x*n2 + v3.x*n3);
                acc.y += (v0.y*n0 + v1.y*n1) + (v2.y*n2 + v3.y*n3);
                acc.z += (v0.z*n0 + v1.z*n1) + (v2.z*n2 + v3.z*n3);
                acc.w += (v0.w*n0 + v1.w*n1) + (v2.w*n2 + v3.w*n3);
            }
            for (; e < end; e++) {
                int s0 = g_csrc[e];
                float n0 = g_deg[s0];
                float4 v = xw4[(size_t)s0 * 32 + lane];
                acc.x += v.x*n0; acc.y += v.y*n0; acc.z += v.z*n0; acc.w += v.w*n0;
            }
        }

        float4 m = make_float4(acc.x * nd + bb.x, acc.y * nd + bb.y,
                               acc.z * nd + bb.z, acc.w * nd + bb.w);

        size_t off = (size_t)gw * D;
        if (stage) {   // f1 only safe after sync (agg0 is 2 launches back)
            xv = ((const float4*)(g_f1 + off))[lane];
            xs = xv.x*xv.x + xv.y*xv.y + xv.z*xv.z + xv.w*xv.w;
        }

        float ms = m.x*m.x + m.y*m.y + m.z*m.z + m.w*m.w;
#pragma unroll
        for (int o = 16; o; o >>= 1) {
            ms += __shfl_xor_sync(0xFFFFFFFFu, ms, o);
            if (stage) xs += __shfl_xor_sync(0xFFFFFFFFu, xs, o);
        }
        float coef = sc * sqrtf(xs) / fmaxf(sqrtf(ms), 1e-12f);

        r.x = gelu_exact(xv.x + coef * m.x);
        r.y = gelu_exact(xv.y + coef * m.y);
        r.z = gelu_exact(xv.z + coef * m.z);
        r.w = gelu_exact(xv.w + coef * m.w);

        if (stage) {
            float4 rv = ((const float4*)(g_xT + off))[lane];
            r.x += rv.x; r.y += rv.y; r.z += rv.z; r.w += rv.w;
        }
        float* out = stage ? g_y : g_f1;
        ((float4*)(out + off))[lane] = r;
    }

    if (stage) {
        if (active) {
            int c0 = lane * 4;
            atomicAdd(&s_cs [c0    ], r.x); atomicAdd(&s_cs2[c0    ], r.x * r.x);
            atomicAdd(&s_cs [c0 + 1], r.y); atomicAdd(&s_cs2[c0 + 1], r.y * r.y);
            atomicAdd(&s_cs [c0 + 2], r.z); atomicAdd(&s_cs2[c0 + 2], r.z * r.z);
            atomicAdd(&s_cs [c0 + 3], r.w); atomicAdd(&s_cs2[c0 + 3], r.w * r.w);
        }
        __syncthreads();
        if (threadIdx.x < D) {
            atomicAdd(&g_cs [threadIdx.x], s_cs [threadIdx.x]);
            atomicAdd(&g_cs2[threadIdx.x], s_cs2[threadIdx.x]);
        }
    }
}

// ---------------- finalize: GraphNorm + GELU, float4 (+ g_hist restore) ----
// PDL consumer: sync at top; g_hist restore stays post-sync (agg1 reads it).
__global__ void k_final(const float* __restrict__ gnw,
                        const float* __restrict__ gnb,
                        const float* __restrict__ gnm,
                        float* __restrict__ out) {
    cudaGridDependencySynchronize();
    const float invN = 1.0f / (float)N_NODES;
    int gtid = blockIdx.x * blockDim.x + threadIdx.x;
    int gstride = gridDim.x * blockDim.x;
    for (int i = gtid; i < N_NODES; i += gstride) g_hist[i] = 0;
    const int total4 = N_NODES * D / 4;
    for (int q = gtid; q < total4; q += gstride) {
        int c0 = (q * 4) & (D - 1);
        float4 y  = ((const float4*)g_y)[q];
        float4 w4  = *(const float4*)&gnw[c0];
        float4 b4  = *(const float4*)&gnb[c0];
        float4 ms4 = *(const float4*)&gnm[c0];
        float4 cs  = *(const float4*)&g_cs[c0];
        float4 cs2 = *(const float4*)&g_cs2[c0];
        float4 o;
        {
            float mean = cs.x * invN, ey2 = cs2.x * invN, msc = ms4.x;
            float var = ey2 - 2.0f*msc*mean*mean + msc*msc*mean*mean;
            o.x = gelu_exact(w4.x * (y.x - mean*msc) * rsqrtf(var + 1e-5f) + b4.x);
        }
        {
            float mean = cs.y * invN, ey2 = cs2.y * invN, msc = ms4.y;
            float var = ey2 - 2.0f*msc*mean*mean + msc*msc*mean*mean;
            o.y = gelu_exact(w4.y * (y.y - mean*msc) * rsqrtf(var + 1e-5f) + b4.y);
        }
        {
            float mean = cs.z * invN, ey2 = cs2.z * invN, msc = ms4.z;
            float var = ey2 - 2.0f*msc*mean*mean + msc*msc*mean*mean;
            o.z = gelu_exact(w4.z * (y.z - mean*msc) * rsqrtf(var + 1e-5f) + b4.z);
        }
        {
            float mean = cs.w * invN, ey2 = cs2.w * invN, msc = ms4.w;
            float var = ey2 - 2.0f*msc*mean*mean + msc*msc*mean*mean;
            o.w = gelu_exact(w4.w * (y.w - mean*msc) * rsqrtf(var + 1e-5f) + b4.w);
        }
        ((float4*)out)[q] = o;
    }
}

// ---------------- launch ----------------------------------------------------
extern "C" void kernel_launch(void* const* d_in, const int* in_sizes, int n_in,
                              void* d_out, int out_size) {
    const float* X   = (const float*)d_in[0];
    const int*   ei  = (const int*)  d_in[1];     // int32 (JAX x64 disabled)
    const float* W1  = (const float*)d_in[2];
    const float* b1  = (const float*)d_in[3];
    const float* s1  = (const float*)d_in[4];
    const float* W2  = (const float*)d_in[5];
    const float* b2  = (const float*)d_in[6];
    const float* s2  = (const float*)d_in[7];
    const float* gnw = (const float*)d_in[8];
    const float* gnb = (const float*)d_in[9];
    const float* gnm = (const float*)d_in[10];
    float* out = (float*)d_out;

    const int TB = 256;
    int gemm_blocks = (N_NODES + 127) / 128;
    int agg_blocks  = (N_NODES * 32 + 511) / 512;
    dim3 tg((N_NODES + 31) / 32, D / 32);

    cudaStream_t se;                       // edge-pipeline branch
    cudaStreamCreateWithFlags(&se, cudaStreamNonBlocking);
    cudaEvent_t evFork, evJoin;
    cudaEventCreateWithFlags(&evFork, cudaEventDisableTiming);
    cudaEventCreateWithFlags(&evJoin, cudaEventDisableTiming);

    // PDL launch attribute (programmatic stream serialization)
    cudaLaunchAttribute pdl;
    pdl.id = cudaLaunchAttributeProgrammaticStreamSerialization;
    pdl.val.programmaticStreamSerializationAllowed = 1;

    // fork: edge pipeline on se, dense pipeline on default stream
    cudaEventRecord(evFork, 0);
    cudaStreamWaitEvent(se, evFork, 0);

    // branch A (se): CSR build + dinv
    k_deg   <<<(N_EDGES + TB - 1) / TB, TB, 0, se>>>(ei);
    k_scan1 <<<N_SBLK, SCAN_B, 0, se>>>();
    k_scan3 <<<(N_NODES + TB - 1) / TB, TB, 0, se>>>();
    k_fill  <<<(N_EDGES + TB - 1) / TB, TB, 0, se>>>(ei);
    cudaEventRecord(evJoin, se);

    // branch B (default): transpose + raw GEMM layer 1 (PDL)
    k_transpose<<<tg, dim3(32, 8)>>>(X);
    {
        cudaLaunchConfig_t cfg = {};
        cfg.gridDim = dim3(gemm_blocks); cfg.blockDim = dim3(TB);
        cfg.stream = 0; cfg.attrs = &pdl; cfg.numAttrs = 1;
        cudaLaunchKernelEx(&cfg, k_gemm, 0, W1);
    }

    // join (full edge — agg0's pre-sync reads branch A data)
    cudaStreamWaitEvent(0, evJoin, 0);

    // ---- layer 1 aggregation (PDL w.r.t. gemm1) ----
    {
        cudaLaunchConfig_t cfg = {};
        cfg.gridDim = dim3(agg_blocks); cfg.blockDim = dim3(512);
        cfg.stream = 0; cfg.attrs = &pdl; cfg.numAttrs = 1;
        cudaLaunchKernelEx(&cfg, k_agg, 0, b1, s1);
    }

    // ---- layer 2 GEMM (PDL w.r.t. agg0) ----
    {
        cudaLaunchConfig_t cfg = {};
        cfg.gridDim = dim3(gemm_blocks); cfg.blockDim = dim3(TB);
        cfg.stream = 0; cfg.attrs = &pdl; cfg.numAttrs = 1;
        cudaLaunchKernelEx(&cfg, k_gemm, 1, W2);
    }

    // ---- layer 2 aggregation (PDL w.r.t. gemm2) ----
    {
        cudaLaunchConfig_t cfg = {};
        cfg.gridDim = dim3(agg_blocks); cfg.blockDim = dim3(512);
        cfg.stream = 0; cfg.attrs = &pdl; cfg.numAttrs = 1;
        cudaLaunchKernelEx(&cfg, k_agg, 1, b2, s2);
    }

    // ---- GraphNorm + GELU (PDL w.r.t. agg1) ----
    {
        cudaLaunchConfig_t cfg = {};
        cfg.gridDim = dim3(2048); cfg.blockDim = dim3(TB);
        cfg.stream = 0; cfg.attrs = &pdl; cfg.numAttrs = 1;
        cudaLaunchKernelEx(&cfg, k_final, gnw, gnb, gnm, out);
    }

    cudaEventDestroy(evFork);
    cudaEventDestroy(evJoin);
    cudaStreamDestroy(se);
}

// round 16
// speedup vs baseline: 1.0398x; 1.0398x over previous
#include <cuda_runtime.h>
#include <math.h>

#define N_NODES 50000
#define N_EDGES 800000
#define D 128
#define SCAN_B 1024
#define N_SBLK ((N_NODES + SCAN_B - 1) / SCAN_B)   // 49

// ---------------- scratch (device globals; self-restoring across replays) --
__device__ float g_xT [(size_t)N_NODES * D];   // X transposed: [N,128]
__device__ float g_xw [(size_t)N_NODES * D];   // GEMM out (L1 raw, L2 pre-scaled)
__device__ float g_f1 [(size_t)N_NODES * D];   // layer-1 output
__device__ float g_y  [(size_t)N_NODES * D];   // layer-2 output (+residual)
__device__ float g_deg[N_NODES];               // dinv = rsqrt(1 + in_deg)
__device__ int   g_hist[N_NODES];              // in-degree (zeroed by k_final)
__device__ int   g_rowstart[N_NODES];          // CSR row starts (by dst)
__device__ int   g_epos[N_EDGES];              // per-edge slot within dst row
__device__ int   g_csrc[N_EDGES];              // CSR src indices
__device__ int   g_bsum[64];                   // scan block sums
__device__ float g_cs [D];                     // col sum of y  (zeroed by gemm L1)
__device__ float g_cs2[D];                     // col sum of y^2

// GELU exact via erff (short polynomial; ~1e-7 abs diff vs normcdff)
__device__ __forceinline__ float gelu_exact(float v) {
    return 0.5f * v * (1.0f + erff(v * 0.70710678118654752f));
}

__device__ __forceinline__ void fma2(unsigned long long& acc,
                                     unsigned long long a,
                                     unsigned long long b) {
    asm("fma.rn.f32x2 %0, %1, %2, %0;" : "+l"(acc) : "l"(a), "l"(b));
}

// ---------------- in-degree histogram + per-edge slot (INT32 edges) --------
// The atomic return value IS the edge's slot within its dst row — saved so
// k_fill needs no atomics at all.
__global__ void k_deg(const int* __restrict__ ei) {
    int e = blockIdx.x * blockDim.x + threadIdx.x;
    if (e < N_EDGES) {
        int d = ei[N_EDGES + e];
        g_epos[e] = atomicAdd(&g_hist[d], 1);
    }
}

// ---------------- scan pass 1 (+ fused dinv = rsqrt(deg+1)) ----------------
__global__ void k_scan1() {
    __shared__ int sh[SCAN_B];
    int t = threadIdx.x;
    int i = blockIdx.x * SCAN_B + t;
    int v = (i < N_NODES) ? g_hist[i] : 0;
    if (i < N_NODES) g_deg[i] = rsqrtf((float)v + 1.0f);
    sh[t] = v;
    __syncthreads();
    for (int off = 1; off < SCAN_B; off <<= 1) {
        int x = (t >= off) ? sh[t - off] : 0;
        __syncthreads();
        sh[t] += x;
        __syncthreads();
    }
    if (i < N_NODES) g_rowstart[i] = sh[t] - v;
    if (t == SCAN_B - 1) g_bsum[blockIdx.x] = sh[t];
}

// ---------------- scan pass 2+3 fused: block offsets + apply ----------------
__global__ void k_scan3() {
    __shared__ int sb[64];
    int t = threadIdx.x;
    if (t < 64) sb[t] = (t < N_SBLK) ? g_bsum[t] : 0;
    __syncthreads();
#pragma unroll
    for (int off = 1; off < 64; off <<= 1) {
        int x = (t < 64 && t >= off) ? sb[t - off] : 0;
        __syncthreads();
        if (t < 64) sb[t] += x;
        __syncthreads();
    }
    int i = blockIdx.x * blockDim.x + t;
    if (i < N_NODES) {
        int blk = i / SCAN_B;
        int add = blk ? sb[blk - 1] : 0;
        g_rowstart[i] += add;
    }
}

// ---------------- CSR fill: atomic-free scatter ------------------------------
__global__ void k_fill(const int* __restrict__ ei) {
    int e = blockIdx.x * blockDim.x + threadIdx.x;
    if (e < N_EDGES) {
        int s = ei[e];
        int d = ei[N_EDGES + e];
        g_csrc[g_rowstart[d] + g_epos[e]] = s;
    }
}

// ---------------- transpose X [128,N] -> xT [N,128] ------------------------
__global__ void k_transpose(const float* __restrict__ X) {
    __shared__ float s[32][33];
    int n0 = blockIdx.x * 32;
    int f0 = blockIdx.y * 32;
    int tx = threadIdx.x, ty = threadIdx.y;          // (32, 8)
    int n = n0 + tx;
#pragma unroll
    for (int i = 0; i < 4; i++) {
        int f = f0 + ty + i * 8;
        if (n < N_NODES) s[ty + i * 8][tx] = X[(size_t)f * N_NODES + n];
    }
    __syncthreads();
#pragma unroll
    for (int i = 0; i < 4; i++) {
        int n2 = n0 + ty + i * 8;
        int f2 = f0 + tx;
        if (n2 < N_NODES) g_xT[(size_t)n2 * D + f2] = s[tx][ty + i * 8];
    }
}

// ---------------- GEMM (f32x2) ----------------------------------------------
// Layer 1 (src_sel=0): g_xw = A @ W          (raw; dinv applied in agg stage 0)
// Layer 2 (src_sel=1): g_xw = (A @ W)*dinv   (pre-scaled fast path)
__global__ void __launch_bounds__(256) k_gemm(int src_sel,
                                              const float* __restrict__ W) {
    const float* __restrict__ A = src_sel ? g_f1 : g_xT;
    if (src_sel == 0 && blockIdx.x == 0 && threadIdx.x < D) {
        g_cs[threadIdx.x] = 0.0f;
        g_cs2[threadIdx.x] = 0.0f;
    }
    __shared__ float2 As2[128][16];    // 16 KB: (a,a) pairs, 16-col k-chunk
    __shared__ float  Ws[16][132];     // 8.25 KB padded
    int t  = threadIdx.x;
    int tx = t & 15;                   // column group (8 cols)
    int ty = t >> 4;                   // node group (8 nodes)
    int nbase = blockIdx.x * 128;

    unsigned long long acc[8][4];
#pragma unroll
    for (int i = 0; i < 8; i++)
#pragma unroll
        for (int p = 0; p < 4; p++) acc[i][p] = 0ull;

    for (int fc = 0; fc < D; fc += 16) {
#pragma unroll
        for (int k = 0; k < 8; k++) {           // 128x16 A chunk (dup pairs)
            int idx = t + k * 256;
            int r = idx >> 4, c = idx & 15;
            int n = nbase + r;
            float v = (n < N_NODES) ? A[(size_t)n * D + fc + c] : 0.0f;
            As2[r][c] = make_float2(v, v);
        }
#pragma unroll
        for (int k = 0; k < 8; k++) {           // 16x128 W chunk
            int idx = t + k * 256;
            int r = idx >> 7, c = idx & 127;
            Ws[r][c] = W[(fc + r) * D + c];
        }
        __syncthreads();
#pragma unroll
        for (int ff = 0; ff < 16; ff++) {
            const unsigned long long* wrow =
                (const unsigned long long*)&Ws[ff][tx * 8];
            unsigned long long w0 = wrow[0];
            unsigned long long w1 = wrow[1];
            unsigned long long w2 = wrow[2];
            unsigned long long w3 = wrow[3];
#pragma unroll
            for (int i = 0; i < 8; i++) {
                unsigned long long a2 =
                    *(const unsigned long long*)&As2[ty * 8 + i][ff];
                fma2(acc[i][0], a2, w0);
                fma2(acc[i][1], a2, w1);
                fma2(acc[i][2], a2, w2);
                fma2(acc[i][3], a2, w3);
            }
        }
        __syncthreads();
    }

#pragma unroll
    for (int i = 0; i < 8; i++) {
        int node = nbase + ty * 8 + i;
        if (node >= N_NODES) continue;
        float di = src_sel ? g_deg[node] : 1.0f;
        size_t off = (size_t)node * D + tx * 8;
        float2 p0 = *(float2*)&acc[i][0];
        float2 p1 = *(float2*)&acc[i][1];
        float2 p2 = *(float2*)&acc[i][2];
        float2 p3 = *(float2*)&acc[i][3];
        ((float4*)(g_xw + off))[0] =
            make_float4(p0.x * di, p0.y * di, p1.x * di, p1.y * di);
        ((float4*)(g_xw + off))[1] =
            make_float4(p2.x * di, p2.y * di, p3.x * di, p3.y * di);
    }
}

// ---------------- fused CSR gather + MessageNorm + GELU (+stats) -----------
// stage 0: xw raw   -> msg = dinv[d]*(dinv[d]*xw[d] + sum dinv[s]*xw[s]) + b
// stage 1: xw scaled-> msg = dinv[d]*(xw[d] + sum xw[s]) + b   (+res, +stats)
// CSR index loads vectorized (int4 after 4-alignment head loop).
__global__ void __launch_bounds__(512) k_agg(int stage,
                                             const float* __restrict__ bias,
                                             const float* __restrict__ scale) {
    __shared__ float s_cs[D], s_cs2[D];
    if (stage) {
        if (threadIdx.x < D) { s_cs[threadIdx.x] = 0.0f; s_cs2[threadIdx.x] = 0.0f; }
        __syncthreads();
    }

    int gw = (blockIdx.x * blockDim.x + threadIdx.x) >> 5;
    int lane = threadIdx.x & 31;
    bool active = gw < N_NODES;
    float4 r = make_float4(0.f, 0.f, 0.f, 0.f);

    if (active) {
        const float4* xw4 = (const float4*)g_xw;
        float nd = g_deg[gw];
        float4 acc = xw4[(size_t)gw * 32 + lane];       // self-loop term
        if (!stage) { acc.x *= nd; acc.y *= nd; acc.z *= nd; acc.w *= nd; }
        int rs  = g_rowstart[gw];
        int end = rs + g_hist[gw];
        int e = rs;
        if (stage) {
            // head: align e to 4 for int4 index loads
            for (; e < end && (e & 3); e++) {
                float4 v = xw4[(size_t)g_csrc[e] * 32 + lane];
                acc.x += v.x; acc.y += v.y; acc.z += v.z; acc.w += v.w;
            }
            for (; e + 8 <= end; e += 8) {
                int4 ia = *(const int4*)&g_csrc[e];
                int4 ib = *(const int4*)&g_csrc[e + 4];
                float4 v0 = xw4[(size_t)ia.x * 32 + lane];
                float4 v1 = xw4[(size_t)ia.y * 32 + lane];
                float4 v2 = xw4[(size_t)ia.z * 32 + lane];
                float4 v3 = xw4[(size_t)ia.w * 32 + lane];
                float4 v4 = xw4[(size_t)ib.x * 32 + lane];
                float4 v5 = xw4[(size_t)ib.y * 32 + lane];
                float4 v6 = xw4[(size_t)ib.z * 32 + lane];
                float4 v7 = xw4[(size_t)ib.w * 32 + lane];
                acc.x += ((v0.x + v1.x) + (v2.x + v3.x)) + ((v4.x + v5.x) + (v6.x + v7.x));
                acc.y += ((v0.y + v1.y) + (v2.y + v3.y)) + ((v4.y + v5.y) + (v6.y + v7.y));
                acc.z += ((v0.z + v1.z) + (v2.z + v3.z)) + ((v4.z + v5.z) + (v6.z + v7.z));
                acc.w += ((v0.w + v1.w) + (v2.w + v3.w)) + ((v4.w + v5.w) + (v6.w + v7.w));
            }
            for (; e < end; e++) {
                float4 v = xw4[(size_t)g_csrc[e] * 32 + lane];
                acc.x += v.x; acc.y += v.y; acc.z += v.z; acc.w += v.w;
            }
        } else {
            for (; e < end && (e & 3); e++) {
                int s0 = g_csrc[e];
                float n0 = g_deg[s0];
                float4 v = xw4[(size_t)s0 * 32 + lane];
                acc.x += v.x*n0; acc.y += v.y*n0; acc.z += v.z*n0; acc.w += v.w*n0;
            }
            for (; e + 4 <= end; e += 4) {
                int4 ia = *(const int4*)&g_csrc[e];
                float n0 = g_deg[ia.x], n1 = g_deg[ia.y];
                float n2 = g_deg[ia.z], n3 = g_deg[ia.w];
                float4 v0 = xw4[(size_t)ia.x * 32 + lane];
                float4 v1 = xw4[(size_t)ia.y * 32 + lane];
                float4 v2 = xw4[(size_t)ia.z * 32 + lane];
                float4 v3 = xw4[(size_t)ia.w * 32 + lane];
                acc.x += (v0.x*n0 + v1.x*n1) + (v2.x*n2 + v3.x*n3);
                acc.y += (v0.y*n0 + v1.y*n1) + (v2.y*n2 + v3.y*n3);
                acc.z += (v0.z*n0 + v1.z*n1) + (v2.z*n2 + v3.z*n3);
                acc.w += (v0.w*n0 + v1.w*n1) + (v2.w*n2 + v3.w*n3);
            }
            for (; e < end; e++) {
                int s0 = g_csrc[e];
                float n0 = g_deg[s0];
                float4 v = xw4[(size_t)s0 * 32 + lane];
                acc.x += v.x*n0; acc.y += v.y*n0; acc.z += v.z*n0; acc.w += v.w*n0;
            }
        }

        float4 bb = ((const float4*)bias)[lane];
        float4 m = make_float4(acc.x * nd + bb.x, acc.y * nd + bb.y,
                               acc.z * nd + bb.z, acc.w * nd + bb.w);

        size_t off = (size_t)gw * D;
        const float* xprev = stage ? g_f1 : g_xT;
        float4 xv = ((const float4*)(xprev + off))[lane];

        float ms = m.x*m.x + m.y*m.y + m.z*m.z + m.w*m.w;
        float xs = xv.x*xv.x + xv.y*xv.y + xv.z*xv.z + xv.w*xv.w;
#pragma unroll
        for (int o = 16; o; o >>= 1) {
            ms += __shfl_xor_sync(0xFFFFFFFFu, ms, o);
            xs += __shfl_xor_sync(0xFFFFFFFFu, xs, o);
        }
        float coef = scale[0] * sqrtf(xs) / fmaxf(sqrtf(ms), 1e-12f);

        r.x = gelu_exact(xv.x + coef * m.x);
        r.y = gelu_exact(xv.y + coef * m.y);
        r.z = gelu_exact(xv.z + coef * m.z);
        r.w = gelu_exact(xv.w + coef * m.w);

        if (stage) {
            float4 rv = ((const float4*)(g_xT + off))[lane];
            r.x += rv.x; r.y += rv.y; r.z += rv.z; r.w += rv.w;
        }
        float* out = stage ? g_y : g_f1;
        ((float4*)(out + off))[lane] = r;
    }

    if (stage) {
        if (active) {
            int c0 = lane * 4;
            atomicAdd(&s_cs [c0    ], r.x); atomicAdd(&s_cs2[c0    ], r.x * r.x);
            atomicAdd(&s_cs [c0 + 1], r.y); atomicAdd(&s_cs2[c0 + 1], r.y * r.y);
            atomicAdd(&s_cs [c0 + 2], r.z); atomicAdd(&s_cs2[c0 + 2], r.z * r.z);
            atomicAdd(&s_cs [c0 + 3], r.w); atomicAdd(&s_cs2[c0 + 3], r.w * r.w);
        }
        __syncthreads();
        if (threadIdx.x < D) {
            atomicAdd(&g_cs [threadIdx.x], s_cs [threadIdx.x]);
            atomicAdd(&g_cs2[threadIdx.x], s_cs2[threadIdx.x]);
        }
    }
}

// ---------------- finalize: GraphNorm + GELU, float4 (+ g_hist restore) ----
__global__ void k_final(const float* __restrict__ gnw,
                        const float* __restrict__ gnb,
                        const float* __restrict__ gnm,
                        float* __restrict__ out) {
    const float invN = 1.0f / (float)N_NODES;
    int gtid = blockIdx.x * blockDim.x + threadIdx.x;
    int gstride = gridDim.x * blockDim.x;
    // restore g_hist for next replay
    for (int i = gtid; i < N_NODES; i += gstride) g_hist[i] = 0;
    // GraphNorm + GELU, 4 elems per thread
    const int total4 = N_NODES * D / 4;
    for (int q = gtid; q < total4; q += gstride) {
        int c0 = (q * 4) & (D - 1);
        float4 y  = ((const float4*)g_y)[q];
        float4 w4  = *(const float4*)&gnw[c0];
        float4 b4  = *(const float4*)&gnb[c0];
        float4 ms4 = *(const float4*)&gnm[c0];
        float4 cs  = *(const float4*)&g_cs[c0];
        float4 cs2 = *(const float4*)&g_cs2[c0];
        float4 o;
        {
            float mean = cs.x * invN, ey2 = cs2.x * invN, msc = ms4.x;
            float var = ey2 - 2.0f*msc*mean*mean + msc*msc*mean*mean;
            o.x = gelu_exact(w4.x * (y.x - mean*msc) * rsqrtf(var + 1e-5f) + b4.x);
        }
        {
            float mean = cs.y * invN, ey2 = cs2.y * invN, msc = ms4.y;
            float var = ey2 - 2.0f*msc*mean*mean + msc*msc*mean*mean;
            o.y = gelu_exact(w4.y * (y.y - mean*msc) * rsqrtf(var + 1e-5f) + b4.y);
        }
        {
            float mean = cs.z * invN, ey2 = cs2.z * invN, msc = ms4.z;
            float var = ey2 - 2.0f*msc*mean*mean + msc*msc*mean*mean;
            o.z = gelu_exact(w4.z * (y.z - mean*msc) * rsqrtf(var + 1e-5f) + b4.z);
        }
        {
            float mean = cs.w * invN, ey2 = cs2.w * invN, msc = ms4.w;
            float var = ey2 - 2.0f*msc*mean*mean + msc*msc*mean*mean;
            o.w = gelu_exact(w4.w * (y.w - mean*msc) * rsqrtf(var + 1e-5f) + b4.w);
        }
        ((float4*)out)[q] = o;
    }
}

// ---------------- launch ----------------------------------------------------
extern "C" void kernel_launch(void* const* d_in, const int* in_sizes, int n_in,
                              void* d_out, int out_size) {
    const float* X   = (const float*)d_in[0];
    const int*   ei  = (const int*)  d_in[1];     // int32 (JAX x64 disabled)
    const float* W1  = (const float*)d_in[2];
    const float* b1  = (const float*)d_in[3];
    const float* s1  = (const float*)d_in[4];
    const float* W2  = (const float*)d_in[5];
    const float* b2  = (const float*)d_in[6];
    const float* s2  = (const float*)d_in[7];
    const float* gnw = (const float*)d_in[8];
    const float* gnb = (const float*)d_in[9];
    const float* gnm = (const float*)d_in[10];
    float* out = (float*)d_out;

    const int TB = 256;
    int gemm_blocks = (N_NODES + 127) / 128;
    int agg_blocks  = (N_NODES * 32 + 511) / 512;
    dim3 tg((N_NODES + 31) / 32, D / 32);

    cudaStream_t se;                       // edge-pipeline branch
    cudaStreamCreateWithFlags(&se, cudaStreamNonBlocking);
    cudaEvent_t evFork, evJoin;
    cudaEventCreateWithFlags(&evFork, cudaEventDisableTiming);
    cudaEventCreateWithFlags(&evJoin, cudaEventDisableTiming);

    // fork: edge pipeline on se, dense pipeline on default stream
    cudaEventRecord(evFork, 0);
    cudaStreamWaitEvent(se, evFork, 0);

    // branch A (se): CSR build + dinv (fill is atomic-free now)
    k_deg   <<<(N_EDGES + TB - 1) / TB, TB, 0, se>>>(ei);
    k_scan1 <<<N_SBLK, SCAN_B, 0, se>>>();
    k_scan3 <<<(N_NODES + TB - 1) / TB, TB, 0, se>>>();
    k_fill  <<<(N_EDGES + TB - 1) / TB, TB, 0, se>>>(ei);
    cudaEventRecord(evJoin, se);

    // branch B (default): transpose + raw GEMM layer 1
    k_transpose<<<tg, dim3(32, 8)>>>(X);
    k_gemm <<<gemm_blocks, TB>>>(0, W1);

    // join
    cudaStreamWaitEvent(0, evJoin, 0);

    // ---- layer 1 aggregation (applies dinv per edge) ----
    k_agg  <<<agg_blocks, 512>>>(0, b1, s1);

    // ---- layer 2 (pre-scaled path) ----
    k_gemm <<<gemm_blocks, TB>>>(1, W2);
    k_agg  <<<agg_blocks, 512>>>(1, b2, s2);

    // ---- GraphNorm + GELU ----
    k_final<<<2048, TB>>>(gnw, gnb, gnm, out);

    cudaEventDestroy(evFork);
    cudaEventDestroy(evJoin);
    cudaStreamDestroy(se);
}

// round 17
// speedup vs baseline: 1.0688x; 1.0280x over previous
#include <cuda_runtime.h>
#include <math.h>

#define N_NODES 50000
#define N_EDGES 800000
#define D 128
#define SCAN_B 1024
#define N_SBLK ((N_NODES + SCAN_B - 1) / SCAN_B)   // 49

// ---------------- scratch (device globals; self-restoring across replays) --
__device__ float g_xT [(size_t)N_NODES * D];   // X transposed: [N,128]
__device__ float g_xw [(size_t)N_NODES * D];   // GEMM out, pre-scaled by dinv[n]
__device__ float g_f1 [(size_t)N_NODES * D];   // layer-1 output
__device__ float g_y  [(size_t)N_NODES * D];   // layer-2 output (+residual)
__device__ float g_deg[N_NODES];               // dinv = rsqrt(1 + in_deg)
__device__ int   g_hist[N_NODES];              // in-degree (zeroed by k_final)
__device__ int   g_rowstart[N_NODES];          // CSR row starts (by dst)
__device__ int   g_epos[N_EDGES];              // per-edge slot within dst row
__device__ int   g_csrc[N_EDGES];              // CSR src indices
__device__ int   g_bsum[64];                   // scan block sums
__device__ float g_cs [D];                     // col sum of y  (zeroed by gemm L1)
__device__ float g_cs2[D];                     // col sum of y^2

// GELU exact via erff (short polynomial; ~1e-7 abs diff vs normcdff)
__device__ __forceinline__ float gelu_exact(float v) {
    return 0.5f * v * (1.0f + erff(v * 0.70710678118654752f));
}

__device__ __forceinline__ void fma2(unsigned long long& acc,
                                     unsigned long long a,
                                     unsigned long long b) {
    asm("fma.rn.f32x2 %0, %1, %2, %0;" : "+l"(acc) : "l"(a), "l"(b));
}

// ---------------- in-degree histogram + per-edge slot (INT32 edges) --------
__global__ void k_deg(const int* __restrict__ ei) {
    int e = blockIdx.x * blockDim.x + threadIdx.x;
    if (e < N_EDGES) {
        int d = ei[N_EDGES + e];
        g_epos[e] = atomicAdd(&g_hist[d], 1);
    }
}

// ---------------- scan pass 1 (+ fused dinv = rsqrt(deg+1)) ----------------
__global__ void k_scan1() {
    __shared__ int sh[SCAN_B];
    int t = threadIdx.x;
    int i = blockIdx.x * SCAN_B + t;
    int v = (i < N_NODES) ? g_hist[i] : 0;
    if (i < N_NODES) g_deg[i] = rsqrtf((float)v + 1.0f);
    sh[t] = v;
    __syncthreads();
    for (int off = 1; off < SCAN_B; off <<= 1) {
        int x = (t >= off) ? sh[t - off] : 0;
        __syncthreads();
        sh[t] += x;
        __syncthreads();
    }
    if (i < N_NODES) g_rowstart[i] = sh[t] - v;
    if (t == SCAN_B - 1) g_bsum[blockIdx.x] = sh[t];
}

// ---------------- scan pass 2+3 fused: block offsets + apply ----------------
__global__ void k_scan3() {
    __shared__ int sb[64];
    int t = threadIdx.x;
    if (t < 64) sb[t] = (t < N_SBLK) ? g_bsum[t] : 0;
    __syncthreads();
#pragma unroll
    for (int off = 1; off < 64; off <<= 1) {
        int x = (t < 64 && t >= off) ? sb[t - off] : 0;
        __syncthreads();
        if (t < 64) sb[t] += x;
        __syncthreads();
    }
    int i = blockIdx.x * blockDim.x + t;
    if (i < N_NODES) {
        int blk = i / SCAN_B;
        int add = blk ? sb[blk - 1] : 0;
        g_rowstart[i] += add;
    }
}

// ---------------- CSR fill: atomic-free scatter ------------------------------
__global__ void k_fill(const int* __restrict__ ei) {
    int e = blockIdx.x * blockDim.x + threadIdx.x;
    if (e < N_EDGES) {
        int s = ei[e];
        int d = ei[N_EDGES + e];
        g_csrc[g_rowstart[d] + g_epos[e]] = s;
    }
}

// ---------------- transpose X [128,N] -> xT [N,128] ------------------------
__global__ void k_transpose(const float* __restrict__ X) {
    __shared__ float s[32][33];
    int n0 = blockIdx.x * 32;
    int f0 = blockIdx.y * 32;
    int tx = threadIdx.x, ty = threadIdx.y;          // (32, 8)
    int n = n0 + tx;
#pragma unroll
    for (int i = 0; i < 4; i++) {
        int f = f0 + ty + i * 8;
        if (n < N_NODES) s[ty + i * 8][tx] = X[(size_t)f * N_NODES + n];
    }
    __syncthreads();
#pragma unroll
    for (int i = 0; i < 4; i++) {
        int n2 = n0 + ty + i * 8;
        int f2 = f0 + tx;
        if (n2 < N_NODES) g_xT[(size_t)n2 * D + f2] = s[tx][ty + i * 8];
    }
}

// ---------------- GEMM (f32x2): g_xw = (A @ W) * dinv (both layers) --------
// gemm1 now waits on evDeg (dinv ready), so both layers pre-scale.
__global__ void __launch_bounds__(256) k_gemm(int src_sel,
                                              const float* __restrict__ W) {
    const float* __restrict__ A = src_sel ? g_f1 : g_xT;
    if (src_sel == 0 && blockIdx.x == 0 && threadIdx.x < D) {
        g_cs[threadIdx.x] = 0.0f;
        g_cs2[threadIdx.x] = 0.0f;
    }
    __shared__ float2 As2[128][16];    // 16 KB: (a,a) pairs, 16-col k-chunk
    __shared__ float  Ws[16][132];     // 8.25 KB padded
    int t  = threadIdx.x;
    int tx = t & 15;                   // column group (8 cols)
    int ty = t >> 4;                   // node group (8 nodes)
    int nbase = blockIdx.x * 128;

    unsigned long long acc[8][4];
#pragma unroll
    for (int i = 0; i < 8; i++)
#pragma unroll
        for (int p = 0; p < 4; p++) acc[i][p] = 0ull;

    for (int fc = 0; fc < D; fc += 16) {
#pragma unroll
        for (int k = 0; k < 8; k++) {           // 128x16 A chunk (dup pairs)
            int idx = t + k * 256;
            int r = idx >> 4, c = idx & 15;
            int n = nbase + r;
            float v = (n < N_NODES) ? A[(size_t)n * D + fc + c] : 0.0f;
            As2[r][c] = make_float2(v, v);
        }
#pragma unroll
        for (int k = 0; k < 8; k++) {           // 16x128 W chunk
            int idx = t + k * 256;
            int r = idx >> 7, c = idx & 127;
            Ws[r][c] = W[(fc + r) * D + c];
        }
        __syncthreads();
#pragma unroll
        for (int ff = 0; ff < 16; ff++) {
            const unsigned long long* wrow =
                (const unsigned long long*)&Ws[ff][tx * 8];
            unsigned long long w0 = wrow[0];
            unsigned long long w1 = wrow[1];
            unsigned long long w2 = wrow[2];
            unsigned long long w3 = wrow[3];
#pragma unroll
            for (int i = 0; i < 8; i++) {
                unsigned long long a2 =
                    *(const unsigned long long*)&As2[ty * 8 + i][ff];
                fma2(acc[i][0], a2, w0);
                fma2(acc[i][1], a2, w1);
                fma2(acc[i][2], a2, w2);
                fma2(acc[i][3], a2, w3);
            }
        }
        __syncthreads();
    }

#pragma unroll
    for (int i = 0; i < 8; i++) {
        int node = nbase + ty * 8 + i;
        if (node >= N_NODES) continue;
        float di = g_deg[node];
        size_t off = (size_t)node * D + tx * 8;
        float2 p0 = *(float2*)&acc[i][0];
        float2 p1 = *(float2*)&acc[i][1];
        float2 p2 = *(float2*)&acc[i][2];
        float2 p3 = *(float2*)&acc[i][3];
        ((float4*)(g_xw + off))[0] =
            make_float4(p0.x * di, p0.y * di, p1.x * di, p1.y * di);
        ((float4*)(g_xw + off))[1] =
            make_float4(p2.x * di, p2.y * di, p3.x * di, p3.y * di);
    }
}

// ---------------- fused CSR gather + MessageNorm + GELU (+stats) -----------
// msg = dinv[d]*(xw[d] + sum xw[s]) + b ; xw pre-scaled for both layers.
// stage 1 adds residual + GraphNorm stats.
__global__ void __launch_bounds__(512) k_agg(int stage,
                                             const float* __restrict__ bias,
                                             const float* __restrict__ scale) {
    __shared__ float s_cs[D], s_cs2[D];
    if (stage) {
        if (threadIdx.x < D) { s_cs[threadIdx.x] = 0.0f; s_cs2[threadIdx.x] = 0.0f; }
        __syncthreads();
    }

    int gw = (blockIdx.x * blockDim.x + threadIdx.x) >> 5;
    int lane = threadIdx.x & 31;
    bool active = gw < N_NODES;
    float4 r = make_float4(0.f, 0.f, 0.f, 0.f);

    if (active) {
        const float4* xw4 = (const float4*)g_xw;
        float nd = g_deg[gw];
        float4 acc = xw4[(size_t)gw * 32 + lane];       // self-loop term
        int rs  = g_rowstart[gw];
        int end = rs + g_hist[gw];
        int e = rs;
        // head: align e to 4 for int4 index loads
        for (; e < end && (e & 3); e++) {
            float4 v = xw4[(size_t)g_csrc[e] * 32 + lane];
            acc.x += v.x; acc.y += v.y; acc.z += v.z; acc.w += v.w;
        }
        for (; e + 8 <= end; e += 8) {
            int4 ia = *(const int4*)&g_csrc[e];
            int4 ib = *(const int4*)&g_csrc[e + 4];
            float4 v0 = xw4[(size_t)ia.x * 32 + lane];
            float4 v1 = xw4[(size_t)ia.y * 32 + lane];
            float4 v2 = xw4[(size_t)ia.z * 32 + lane];
            float4 v3 = xw4[(size_t)ia.w * 32 + lane];
            float4 v4 = xw4[(size_t)ib.x * 32 + lane];
            float4 v5 = xw4[(size_t)ib.y * 32 + lane];
            float4 v6 = xw4[(size_t)ib.z * 32 + lane];
            float4 v7 = xw4[(size_t)ib.w * 32 + lane];
            acc.x += ((v0.x + v1.x) + (v2.x + v3.x)) + ((v4.x + v5.x) + (v6.x + v7.x));
            acc.y += ((v0.y + v1.y) + (v2.y + v3.y)) + ((v4.y + v5.y) + (v6.y + v7.y));
            acc.z += ((v0.z + v1.z) + (v2.z + v3.z)) + ((v4.z + v5.z) + (v6.z + v7.z));
            acc.w += ((v0.w + v1.w) + (v2.w + v3.w)) + ((v4.w + v5.w) + (v6.w + v7.w));
        }
        for (; e + 4 <= end; e += 4) {
            int4 ia = *(const int4*)&g_csrc[e];
            float4 v0 = xw4[(size_t)ia.x * 32 + lane];
            float4 v1 = xw4[(size_t)ia.y * 32 + lane];
            float4 v2 = xw4[(size_t)ia.z * 32 + lane];
            float4 v3 = xw4[(size_t)ia.w * 32 + lane];
            acc.x += (v0.x + v1.x) + (v2.x + v3.x);
            acc.y += (v0.y + v1.y) + (v2.y + v3.y);
            acc.z += (v0.z + v1.z) + (v2.z + v3.z);
            acc.w += (v0.w + v1.w) + (v2.w + v3.w);
        }
        for (; e < end; e++) {
            float4 v = xw4[(size_t)g_csrc[e] * 32 + lane];
            acc.x += v.x; acc.y += v.y; acc.z += v.z; acc.w += v.w;
        }

        float4 bb = ((const float4*)bias)[lane];
        float4 m = make_float4(acc.x * nd + bb.x, acc.y * nd + bb.y,
                               acc.z * nd + bb.z, acc.w * nd + bb.w);

        size_t off = (size_t)gw * D;
        const float* xprev = stage ? g_f1 : g_xT;
        float4 xv = ((const float4*)(xprev + off))[lane];

        float ms = m.x*m.x + m.y*m.y + m.z*m.z + m.w*m.w;
        float xs = xv.x*xv.x + xv.y*xv.y + xv.z*xv.z + xv.w*xv.w;
#pragma unroll
        for (int o = 16; o; o >>= 1) {
            ms += __shfl_xor_sync(0xFFFFFFFFu, ms, o);
            xs += __shfl_xor_sync(0xFFFFFFFFu, xs, o);
        }
        float coef = scale[0] * sqrtf(xs) / fmaxf(sqrtf(ms), 1e-12f);

        r.x = gelu_exact(xv.x + coef * m.x);
        r.y = gelu_exact(xv.y + coef * m.y);
        r.z = gelu_exact(xv.z + coef * m.z);
        r.w = gelu_exact(xv.w + coef * m.w);

        if (stage) {
            float4 rv = ((const float4*)(g_xT + off))[lane];
            r.x += rv.x; r.y += rv.y; r.z += rv.z; r.w += rv.w;
        }
        float* out = stage ? g_y : g_f1;
        ((float4*)(out + off))[lane] = r;
    }

    if (stage) {
        if (active) {
            int c0 = lane * 4;
            atomicAdd(&s_cs [c0    ], r.x); atomicAdd(&s_cs2[c0    ], r.x * r.x);
            atomicAdd(&s_cs [c0 + 1], r.y); atomicAdd(&s_cs2[c0 + 1], r.y * r.y);
            atomicAdd(&s_cs [c0 + 2], r.z); atomicAdd(&s_cs2[c0 + 2], r.z * r.z);
            atomicAdd(&s_cs [c0 + 3], r.w); atomicAdd(&s_cs2[c0 + 3], r.w * r.w);
        }
        __syncthreads();
        if (threadIdx.x < D) {
            atomicAdd(&g_cs [threadIdx.x], s_cs [threadIdx.x]);
            atomicAdd(&g_cs2[threadIdx.x], s_cs2[threadIdx.x]);
        }
    }
}

// ---------------- finalize: GraphNorm + GELU, float4 (+ g_hist restore) ----
__global__ void k_final(const float* __restrict__ gnw,
                        const float* __restrict__ gnb,
                        const float* __restrict__ gnm,
                        float* __restrict__ out) {
    const float invN = 1.0f / (float)N_NODES;
    int gtid = blockIdx.x * blockDim.x + threadIdx.x;
    int gstride = gridDim.x * blockDim.x;
    for (int i = gtid; i < N_NODES; i += gstride) g_hist[i] = 0;
    const int total4 = N_NODES * D / 4;
    for (int q = gtid; q < total4; q += gstride) {
        int c0 = (q * 4) & (D - 1);
        float4 y  = ((const float4*)g_y)[q];
        float4 w4  = *(const float4*)&gnw[c0];
        float4 b4  = *(const float4*)&gnb[c0];
        float4 ms4 = *(const float4*)&gnm[c0];
        float4 cs  = *(const float4*)&g_cs[c0];
        float4 cs2 = *(const float4*)&g_cs2[c0];
        float4 o;
        {
            float mean = cs.x * invN, ey2 = cs2.x * invN, msc = ms4.x;
            float var = ey2 - 2.0f*msc*mean*mean + msc*msc*mean*mean;
            o.x = gelu_exact(w4.x * (y.x - mean*msc) * rsqrtf(var + 1e-5f) + b4.x);
        }
        {
            float mean = cs.y * invN, ey2 = cs2.y * invN, msc = ms4.y;
            float var = ey2 - 2.0f*msc*mean*mean + msc*msc*mean*mean;
            o.y = gelu_exact(w4.y * (y.y - mean*msc) * rsqrtf(var + 1e-5f) + b4.y);
        }
        {
            float mean = cs.z * invN, ey2 = cs2.z * invN, msc = ms4.z;
            float var = ey2 - 2.0f*msc*mean*mean + msc*msc*mean*mean;
            o.z = gelu_exact(w4.z * (y.z - mean*msc) * rsqrtf(var + 1e-5f) + b4.z);
        }
        {
            float mean = cs.w * invN, ey2 = cs2.w * invN, msc = ms4.w;
            float var = ey2 - 2.0f*msc*mean*mean + msc*msc*mean*mean;
            o.w = gelu_exact(w4.w * (y.w - mean*msc) * rsqrtf(var + 1e-5f) + b4.w);
        }
        ((float4*)out)[q] = o;
    }
}

// ---------------- launch ----------------------------------------------------
extern "C" void kernel_launch(void* const* d_in, const int* in_sizes, int n_in,
                              void* d_out, int out_size) {
    const float* X   = (const float*)d_in[0];
    const int*   ei  = (const int*)  d_in[1];     // int32 (JAX x64 disabled)
    const float* W1  = (const float*)d_in[2];
    const float* b1  = (const float*)d_in[3];
    const float* s1  = (const float*)d_in[4];
    const float* W2  = (const float*)d_in[5];
    const float* b2  = (const float*)d_in[6];
    const float* s2  = (const float*)d_in[7];
    const float* gnw = (const float*)d_in[8];
    const float* gnb = (const float*)d_in[9];
    const float* gnm = (const float*)d_in[10];
    float* out = (float*)d_out;

    const int TB = 256;
    int gemm_blocks = (N_NODES + 127) / 128;
    int agg_blocks  = (N_NODES * 32 + 511) / 512;
    dim3 tg((N_NODES + 31) / 32, D / 32);

    cudaStream_t se;                       // edge-pipeline branch
    cudaStreamCreateWithFlags(&se, cudaStreamNonBlocking);
    cudaEvent_t evFork, evDeg, evJoin;
    cudaEventCreateWithFlags(&evFork, cudaEventDisableTiming);
    cudaEventCreateWithFlags(&evDeg,  cudaEventDisableTiming);
    cudaEventCreateWithFlags(&evJoin, cudaEventDisableTiming);

    // fork: edge pipeline on se, dense pipeline on default stream
    cudaEventRecord(evFork, 0);
    cudaStreamWaitEvent(se, evFork, 0);

    // branch A (se): CSR build + dinv (dinv ready after scan1)
    k_deg   <<<(N_EDGES + TB - 1) / TB, TB, 0, se>>>(ei);
    k_scan1 <<<N_SBLK, SCAN_B, 0, se>>>();
    cudaEventRecord(evDeg, se);            // g_deg complete here
    k_scan3 <<<(N_NODES + TB - 1) / TB, TB, 0, se>>>();
    k_fill  <<<(N_EDGES + TB - 1) / TB, TB, 0, se>>>(ei);
    cudaEventRecord(evJoin, se);

    // branch B (default): transpose, then gemm1 (needs dinv for pre-scale)
    k_transpose<<<tg, dim3(32, 8)>>>(X);
    cudaStreamWaitEvent(0, evDeg, 0);
    k_gemm <<<gemm_blocks, TB>>>(0, W1);

    // join (CSR needed by agg)
    cudaStreamWaitEvent(0, evJoin, 0);

    // ---- layer 1 aggregation ----
    k_agg  <<<agg_blocks, 512>>>(0, b1, s1);

    // ---- layer 2 ----
    k_gemm <<<gemm_blocks, TB>>>(1, W2);
    k_agg  <<<agg_blocks, 512>>>(1, b2, s2);

    // ---- GraphNorm + GELU ----
    k_final<<<2048, TB>>>(gnw, gnb, gnm, out);

    cudaEventDestroy(evFork);
    cudaEventDestroy(evDeg);
    cudaEventDestroy(evJoin);
    cudaStreamDestroy(se);
}